// round 13
// baseline (speedup 1.0000x reference)
#include <cuda_runtime.h>
#include <cuda_fp16.h>
#include <cstdint>

#define Vn   20000
#define NNZn 640000
#define Bn   16
#define CINn 128
#define COUTn 128
#define Rn   4
#define Fn   2048   // Bn * CINn

// ---------------- scratch (static device memory; no allocation at runtime) ----------------
__device__ __half g_xh[(size_t)Rn * Vn * Fn];   // 4 Chebyshev terms, each (V, 2048) fp16 (~327 MB)
__device__ __half g_wt[(size_t)COUTn * 512];    // weight transposed: [o][r*128+i] fp16
__device__ int    g_rowptr[Vn + 1];
__device__ int    g_cnt[Vn];                    // zeroed statically; re-zeroed by scan_kernel each call
__device__ int    g_fill[Vn];                   // zeroed statically; re-zeroed by scan_kernel each call
__device__ int2   g_ev[NNZn];                   // packed: {col*256 (uint4 row idx), half2(w,w) bits}

// ---------------- fused prelude: count | transpose | wprep (independent work) ----------------
#define COUNT_BLKS 2500
#define TRANS_BLKS 40000     // (Vn/32) * (Fn/32) = 625 * 64
#define WPREP_BLKS 256
__global__ void __launch_bounds__(256) fused_prelude_kernel(const int* __restrict__ rows,
                                                            const float* __restrict__ x,
                                                            const float* __restrict__ weight) {
    __shared__ float tile[32][33];
    int bid = blockIdx.x;
    int tid = threadIdx.x;
    if (bid < COUNT_BLKS) {
        int j = bid * 256 + tid;
        if (j < NNZn) atomicAdd(&g_cnt[rows[j]], 1);
    } else if (bid < COUNT_BLKS + TRANS_BLKS) {
        int b2 = bid - COUNT_BLKS;
        int v0 = (b2 % 625) * 32;
        int c0 = (b2 / 625) * 32;
        int tx = tid & 31;
        int ty0 = tid >> 5;          // 0..7
#pragma unroll
        for (int q = 0; q < 4; q++) {
            int ty = ty0 + q * 8;
            tile[ty][tx] = x[(size_t)(c0 + ty) * Vn + (v0 + tx)];
        }
        __syncthreads();
#pragma unroll
        for (int q = 0; q < 4; q++) {
            int ty = ty0 + q * 8;
            g_xh[(size_t)(v0 + ty) * Fn + (c0 + tx)] = __float2half_rn(tile[tx][ty]);
        }
    } else {
        int idx = (bid - COUNT_BLKS - TRANS_BLKS) * 256 + tid;   // 65536 total
        int o = idx >> 9;
        int k = idx & 511;
        g_wt[(size_t)o * 512 + k] = __float2half_rn(weight[(size_t)k * 128 + o]);
    }
}

// ---------------- exclusive scan over 20000 counters (2 barriers), also resets cnt/fill ----------------
__global__ void __launch_bounds__(1024) scan_kernel() {
    __shared__ int wsum[32];
    int t = threadIdx.x;          // 0..1023; threads 0..999 each own 20 rows
    int local[20];
    int s = 0;
    if (t < 1000) {
        int base = t * 20;
#pragma unroll
        for (int k = 0; k < 20; k++) {
            local[k] = g_cnt[base + k];
            s += local[k];
        }
    }
    int lane = t & 31, w = t >> 5;
    int ps = s;
#pragma unroll
    for (int off = 1; off < 32; off <<= 1) {
        int o = __shfl_up_sync(0xffffffff, ps, off);
        if (lane >= off) ps += o;
    }
    if (lane == 31) wsum[w] = ps;
    __syncthreads();
    if (w == 0) {
        int v = wsum[lane];
        int pv = v;
#pragma unroll
        for (int off = 1; off < 32; off <<= 1) {
            int o = __shfl_up_sync(0xffffffff, pv, off);
            if (lane >= off) pv += o;
        }
        wsum[lane] = pv - v;   // exclusive warp offsets
    }
    __syncthreads();
    int excl = wsum[w] + ps - s;   // exclusive prefix for this thread
    if (t < 1000) {
        int base = t * 20;
        int run = excl;
#pragma unroll
        for (int k = 0; k < 20; k++) {
            g_rowptr[base + k] = run;
            run += local[k];
            g_cnt[base + k] = 0;     // reset for next call's count
            g_fill[base + k] = 0;    // reset for this call's scatter
        }
        if (t == 999) g_rowptr[Vn] = run;
    }
}

__global__ void scatter_kernel(const int* __restrict__ rows,
                               const int* __restrict__ cols,
                               const float* __restrict__ vals) {
    int j = blockIdx.x * blockDim.x + threadIdx.x;
    if (j < NNZn) {
        int r = rows[j];
        int p = g_rowptr[r] + atomicAdd(&g_fill[r], 1);
        __half2 h2 = __half2half2(__float2half_rn(vals[j]));
        g_ev[p] = make_int2(cols[j] << 8, *reinterpret_cast<int*>(&h2));  // uint4 row index (256/row)
    }
}

// ---------------- SpMM (CSR gather), fp16 rows, LDG.128 gathers, half2 staging (R6 config) ----------------
__device__ __forceinline__ void hacc4(__half2* st, const uint4& r, __half2 w2) {
    const __half2* h = reinterpret_cast<const __half2*>(&r);
    st[0] = __hfma2(w2, h[0], st[0]);
    st[1] = __hfma2(w2, h[1], st[1]);
    st[2] = __hfma2(w2, h[2], st[2]);
    st[3] = __hfma2(w2, h[3], st[3]);
}

__device__ __forceinline__ void flush_st(float* acc, __half2* st) {
#pragma unroll
    for (int q = 0; q < 4; q++) {
        float2 fv = __half22float2(st[q]);
        acc[2 * q]     += fv.x;
        acc[2 * q + 1] += fv.y;
        st[q] = __half2half2(__ushort_as_half(0));
    }
}

__device__ __forceinline__ __half2 evw(const int2& ev) {
    return *reinterpret_cast<const __half2*>(&ev.y);
}

// grid: (Vn, 2), block: 128 threads, each thread one uint4 = 8 halves
template <int MODE>  // 0: xk = L*y ; 1: xk = 2*L*y - xm2
__global__ void __launch_bounds__(128, 9) spmm_kernel(int iy, int im2, int io) {
    const unsigned term = (unsigned)Vn * 256;   // uint4 per term
    const uint4* __restrict__ y4 = reinterpret_cast<const uint4*>(g_xh) + (size_t)iy  * term;
    const uint4* __restrict__ m4 = reinterpret_cast<const uint4*>(g_xh) + (size_t)im2 * term;
    uint4* __restrict__       o4 = reinterpret_cast<uint4*>(g_xh) + (size_t)io * term;

    int v = blockIdx.x;
    unsigned f = blockIdx.y * 128 + threadIdx.x;   // uint4 index 0..255 within the row
    int s = g_rowptr[v], e = g_rowptr[v + 1];

    float acc[8];
#pragma unroll
    for (int q = 0; q < 8; q++) acc[q] = 0.f;
    __half2 st[4];
#pragma unroll
    for (int q = 0; q < 4; q++) st[q] = __half2half2(__ushort_as_half(0));

    int j = s;
    for (; j + 7 < e; j += 8) {
        int2 ev0 = __ldg(&g_ev[j]);
        int2 ev1 = __ldg(&g_ev[j + 1]);
        int2 ev2 = __ldg(&g_ev[j + 2]);
        int2 ev3 = __ldg(&g_ev[j + 3]);
        int2 ev4 = __ldg(&g_ev[j + 4]);
        int2 ev5 = __ldg(&g_ev[j + 5]);
        int2 ev6 = __ldg(&g_ev[j + 6]);
        int2 ev7 = __ldg(&g_ev[j + 7]);
        {
            uint4 r0 = __ldg(&y4[(unsigned)ev0.x + f]);
            uint4 r1 = __ldg(&y4[(unsigned)ev1.x + f]);
            uint4 r2 = __ldg(&y4[(unsigned)ev2.x + f]);
            uint4 r3 = __ldg(&y4[(unsigned)ev3.x + f]);
            hacc4(st, r0, evw(ev0));
            hacc4(st, r1, evw(ev1));
            hacc4(st, r2, evw(ev2));
            hacc4(st, r3, evw(ev3));
        }
        {
            uint4 r0 = __ldg(&y4[(unsigned)ev4.x + f]);
            uint4 r1 = __ldg(&y4[(unsigned)ev5.x + f]);
            uint4 r2 = __ldg(&y4[(unsigned)ev6.x + f]);
            uint4 r3 = __ldg(&y4[(unsigned)ev7.x + f]);
            hacc4(st, r0, evw(ev4));
            hacc4(st, r1, evw(ev5));
            hacc4(st, r2, evw(ev6));
            hacc4(st, r3, evw(ev7));
        }
        flush_st(acc, st);
    }
    for (; j < e; j++) {
        int2 ev = __ldg(&g_ev[j]);
        uint4 r0 = __ldg(&y4[(unsigned)ev.x + f]);
        hacc4(st, r0, evw(ev));
    }
    flush_st(acc, st);

    size_t oi = (size_t)v * 256 + f;
    if (MODE == 1) {
        uint4 mraw = __ldcs(&m4[oi]);
        const __half2* mh = reinterpret_cast<const __half2*>(&mraw);
#pragma unroll
        for (int q = 0; q < 4; q++) {
            float2 m = __half22float2(mh[q]);
            acc[2 * q]     = 2.f * acc[2 * q]     - m.x;
            acc[2 * q + 1] = 2.f * acc[2 * q + 1] - m.y;
        }
    }
    uint4 outv;
    __half2* oh = reinterpret_cast<__half2*>(&outv);
#pragma unroll
    for (int q = 0; q < 4; q++)
        oh[q] = __floats2half2_rn(acc[2 * q], acc[2 * q + 1]);
    __stcs(&o4[oi], outv);
}

// ---------------- fused fp16 GEMM, cp.async double-buffered, split over term pairs ----------------
// TB = term base (0 or 2), K = 256 per part.
// FIRST=1: out = partial + bias ; FIRST=0: out += partial
#define MMA_F16(C, A, Bf)                                                                   \
    asm volatile("mma.sync.aligned.m16n8k16.row.col.f32.f16.f16.f32 "                      \
                 "{%0,%1,%2,%3},{%4,%5,%6,%7},{%8,%9},{%0,%1,%2,%3};"                       \
                 : "+f"((C)[0]), "+f"((C)[1]), "+f"((C)[2]), "+f"((C)[3])                   \
                 : "r"((A)[0]), "r"((A)[1]), "r"((A)[2]), "r"((A)[3]),                      \
                   "r"((Bf)[0]), "r"((Bf)[1]))

#define CP_ASYNC16(dst, src) \
    asm volatile("cp.async.cg.shared.global [%0], [%1], 16;" :: "r"(dst), "l"(src))
#define CP_COMMIT() asm volatile("cp.async.commit_group;")
#define CP_WAIT1()  asm volatile("cp.async.wait_group 1;")
#define CP_WAIT0()  asm volatile("cp.async.wait_group 0;")

// block tile: M=128 (v), N=128 (o), K=256 in 8 chunks of 32 halves, 2-stage cp.async pipeline.
// 256 threads = 8 warps (2 x 4). Tile stride 20 u32 = 80 B (16B-aligned). Pool 40 KB; Cs aliased.
template <int TB, int FIRST>
__global__ void __launch_bounds__(256) gemm_kernel(const float* __restrict__ bias,
                                                   float* __restrict__ out) {
    __shared__ __align__(16) unsigned pool[10240];  // 40 KB
    unsigned* As = pool;                            // [2][128][20]
    unsigned* Ws = pool + 5120;                     // [2][128][20]
    float*    Cs = reinterpret_cast<float*>(pool);  // [128][65] (aliased after compute)

    int tid  = threadIdx.x;
    int lane = tid & 31;
    int warp = tid >> 5;
    int wm   = warp & 1;
    int wn   = warp >> 1;  // 0..3 : 32 o-cols each
    int bb   = blockIdx.y;
    int v0   = blockIdx.x * 128;
    int t    = lane & 3;
    int g    = lane >> 2;

    float c[4][4][4];
#pragma unroll
    for (int nt = 0; nt < 4; nt++) {
        float b0 = 0.f, b1 = 0.f;
        if (FIRST) {
            int o = wn * 32 + nt * 8 + t * 2;
            b0 = bias[o];
            b1 = bias[o + 1];
        }
#pragma unroll
        for (int mt = 0; mt < 4; mt++) {
            c[mt][nt][0] = b0; c[mt][nt][1] = b1;
            c[mt][nt][2] = b0; c[mt][nt][3] = b1;
        }
    }

    // stage issue: A rows clamp to row 0 when v >= Vn (finite garbage, never stored)
    auto issue = [&](int stg) {
        int buf = stg & 1;
        int k0g = TB * 128 + stg * 32;   // global k
        int r   = k0g >> 7;
        int i0  = k0g & 127;
#pragma unroll
        for (int p = 0; p < 2; p++) {
            int idx = tid + p * 256;      // 0..511
            int row = idx >> 2;
            int seg = idx & 3;
            int v   = v0 + row;
            int vc  = v < Vn ? v : 0;
            const __half* src = g_xh + (size_t)(r * Vn + vc) * Fn + bb * 128 + i0 + seg * 8;
            unsigned dst = (unsigned)__cvta_generic_to_shared(As + buf * 2560 + row * 20 + seg * 4);
            CP_ASYNC16(dst, src);
        }
#pragma unroll
        for (int p = 0; p < 2; p++) {
            int idx = tid + p * 256;
            int o   = idx >> 2;
            int seg = idx & 3;
            const __half* src = g_wt + (size_t)o * 512 + k0g + seg * 8;
            unsigned dst = (unsigned)__cvta_generic_to_shared(Ws + buf * 2560 + o * 20 + seg * 4);
            CP_ASYNC16(dst, src);
        }
        CP_COMMIT();
    };

    issue(0);
    for (int stg = 0; stg < 8; stg++) {
        if (stg + 1 < 8) {
            issue(stg + 1);
            CP_WAIT1();
        } else {
            CP_WAIT0();
        }
        __syncthreads();
        int buf = stg & 1;
        const unsigned* Ab = As + buf * 2560;
        const unsigned* Wb = Ws + buf * 2560;
#pragma unroll
        for (int s = 0; s < 2; s++) {           // 2 k-steps of 16 halves
            unsigned bf[4][2];
#pragma unroll
            for (int nt = 0; nt < 4; nt++) {
                int o = wn * 32 + nt * 8 + g;
                bf[nt][0] = Wb[o * 20 + s * 8 + t];
                bf[nt][1] = Wb[o * 20 + s * 8 + t + 4];
            }
#pragma unroll
            for (int mt = 0; mt < 4; mt++) {
                int arow = mt * 32 + wm * 16 + g;
                unsigned a[4];
                a[0] = Ab[arow * 20 + s * 8 + t];
                a[1] = Ab[(arow + 8) * 20 + s * 8 + t];
                a[2] = Ab[arow * 20 + s * 8 + t + 4];
                a[3] = Ab[(arow + 8) * 20 + s * 8 + t + 4];
#pragma unroll
                for (int nt = 0; nt < 4; nt++)
                    MMA_F16(c[mt][nt], a, bf[nt]);
            }
        }
        __syncthreads();
    }

    // stage C into shared as [o][v] for coalesced (B,Cout,V) stores — two passes of 64 rows
#pragma unroll
    for (int p = 0; p < 2; p++) {
#pragma unroll
        for (int mth = 0; mth < 2; mth++) {
            int mt = 2 * p + mth;
#pragma unroll
            for (int nt = 0; nt < 4; nt++) {
                int vr = mth * 32 + wm * 16 + g;     // 0..63 within pass
                int o  = wn * 32 + nt * 8 + t * 2;
                Cs[o * 65 + vr]           = c[mt][nt][0];
                Cs[(o + 1) * 65 + vr]     = c[mt][nt][1];
                Cs[o * 65 + vr + 8]       = c[mt][nt][2];
                Cs[(o + 1) * 65 + vr + 8] = c[mt][nt][3];
            }
        }
        __syncthreads();
        for (int idx = tid; idx < 128 * 64; idx += 256) {
            int o  = idx >> 6;
            int vl = idx & 63;
            int v  = v0 + p * 64 + vl;
            if (v < Vn) {
                size_t oidx = ((size_t)bb * 128 + o) * Vn + v;
                if (FIRST)
                    __stcs(&out[oidx], Cs[o * 65 + vl]);
                else
                    __stcs(&out[oidx], out[oidx] + Cs[o * 65 + vl]);
            }
        }
        __syncthreads();
    }
}

// ---------------- launch: gemm part1 (terms 0,1) overlaps spmm1/spmm2 ----------------
extern "C" void kernel_launch(void* const* d_in, const int* in_sizes, int n_in,
                              void* d_out, int out_size) {
    const float* x        = (const float*)d_in[0];
    const float* weight   = (const float*)d_in[1];
    const float* bias     = (const float*)d_in[2];
    const float* lap_vals = (const float*)d_in[3];
    const int*   lap_rows = (const int*)d_in[4];
    const int*   lap_cols = (const int*)d_in[5];
    float* out = (float*)d_out;

    // one-time host-side objects (no device memory involved)
    static cudaStream_t s1 = nullptr;
    static cudaEvent_t  eFork = nullptr, eJoin = nullptr;
    if (s1 == nullptr) {
        cudaStreamCreateWithFlags(&s1, cudaStreamNonBlocking);
        cudaEventCreateWithFlags(&eFork, cudaEventDisableTiming);
        cudaEventCreateWithFlags(&eJoin, cudaEventDisableTiming);
    }

    // prelude: fused {count | transpose | wprep}, scan (also resets counters), scatter
    fused_prelude_kernel<<<COUNT_BLKS + TRANS_BLKS + WPREP_BLKS, 256>>>(lap_rows, x, weight);
    scan_kernel<<<1, 1024>>>();
    scatter_kernel<<<NNZn / 256, 256>>>(lap_rows, lap_cols, lap_vals);

    // x1 = L x0 — after this, terms 0 and 1 are final
    spmm_kernel<0><<<dim3(Vn, 2), 128>>>(0, 0, 1);

    // fork: gemm part1 (terms 0,1) on side stream, overlapping spmm1/spmm2
    cudaEventRecord(eFork, 0);
    cudaStreamWaitEvent(s1, eFork, 0);
    gemm_kernel<0, 1><<<dim3((Vn + 127) / 128, Bn), 256, 0, s1>>>(bias, out);
    cudaEventRecord(eJoin, s1);

    // main: x2 = 2 L x1 - x0 ; x3 = 2 L x2 - x1
    spmm_kernel<1><<<dim3(Vn, 2), 128>>>(1, 0, 2);
    spmm_kernel<1><<<dim3(Vn, 2), 128>>>(2, 1, 3);

    // join: gemm part2 needs part1's output in place
    cudaStreamWaitEvent(0, eJoin, 0);
    gemm_kernel<2, 0><<<dim3((Vn + 127) / 128, Bn), 256>>>(bias, out);
}

// round 14
// speedup vs baseline: 1.4063x; 1.4063x over previous
#include <cuda_runtime.h>
#include <cuda_fp16.h>
#include <cstdint>

#define Vn   20000
#define NNZn 640000
#define Bn   16
#define CINn 128
#define COUTn 128
#define Rn   4
#define Fn   2048   // Bn * CINn

// ---------------- scratch (static device memory; no allocation at runtime) ----------------
__device__ __half g_xh[(size_t)Rn * Vn * Fn];   // 4 Chebyshev terms, each (V, 2048) fp16 (~327 MB)
__device__ __half g_wt[(size_t)COUTn * 512];    // weight transposed: [o][r*128+i] fp16
__device__ int    g_rowptr[Vn + 1];
__device__ int    g_cnt[Vn];                    // zeroed statically; re-zeroed by scan_kernel each call
__device__ int    g_fill[Vn];                   // zeroed statically; re-zeroed by scan_kernel each call
__device__ int2   g_ev[NNZn];                   // packed: {col*256 (uint4 row idx), half2(w,w) bits}

// ---------------- fused prelude: count | transpose | wprep (independent work) ----------------
#define COUNT_BLKS 2500
#define TRANS_BLKS 40000     // (Vn/32) * (Fn/32) = 625 * 64
#define WPREP_BLKS 256
__global__ void __launch_bounds__(256) fused_prelude_kernel(const int* __restrict__ rows,
                                                            const float* __restrict__ x,
                                                            const float* __restrict__ weight) {
    __shared__ float tile[32][33];
    int bid = blockIdx.x;
    int tid = threadIdx.x;
    if (bid < COUNT_BLKS) {
        int j = bid * 256 + tid;
        if (j < NNZn) atomicAdd(&g_cnt[rows[j]], 1);
    } else if (bid < COUNT_BLKS + TRANS_BLKS) {
        int b2 = bid - COUNT_BLKS;
        int v0 = (b2 % 625) * 32;
        int c0 = (b2 / 625) * 32;
        int tx = tid & 31;
        int ty0 = tid >> 5;          // 0..7
#pragma unroll
        for (int q = 0; q < 4; q++) {
            int ty = ty0 + q * 8;
            tile[ty][tx] = x[(size_t)(c0 + ty) * Vn + (v0 + tx)];
        }
        __syncthreads();
#pragma unroll
        for (int q = 0; q < 4; q++) {
            int ty = ty0 + q * 8;
            g_xh[(size_t)(v0 + ty) * Fn + (c0 + tx)] = __float2half_rn(tile[tx][ty]);
        }
    } else {
        int idx = (bid - COUNT_BLKS - TRANS_BLKS) * 256 + tid;   // 65536 total
        int o = idx >> 9;
        int k = idx & 511;
        g_wt[(size_t)o * 512 + k] = __float2half_rn(weight[(size_t)k * 128 + o]);
    }
}

// ---------------- exclusive scan over 20000 counters (2 barriers), also resets cnt/fill ----------------
__global__ void __launch_bounds__(1024) scan_kernel() {
    __shared__ int wsum[32];
    int t = threadIdx.x;          // 0..1023; threads 0..999 each own 20 rows
    int local[20];
    int s = 0;
    if (t < 1000) {
        int base = t * 20;
#pragma unroll
        for (int k = 0; k < 20; k++) {
            local[k] = g_cnt[base + k];
            s += local[k];
        }
    }
    int lane = t & 31, w = t >> 5;
    int ps = s;
#pragma unroll
    for (int off = 1; off < 32; off <<= 1) {
        int o = __shfl_up_sync(0xffffffff, ps, off);
        if (lane >= off) ps += o;
    }
    if (lane == 31) wsum[w] = ps;
    __syncthreads();
    if (w == 0) {
        int v = wsum[lane];
        int pv = v;
#pragma unroll
        for (int off = 1; off < 32; off <<= 1) {
            int o = __shfl_up_sync(0xffffffff, pv, off);
            if (lane >= off) pv += o;
        }
        wsum[lane] = pv - v;   // exclusive warp offsets
    }
    __syncthreads();
    int excl = wsum[w] + ps - s;   // exclusive prefix for this thread
    if (t < 1000) {
        int base = t * 20;
        int run = excl;
#pragma unroll
        for (int k = 0; k < 20; k++) {
            g_rowptr[base + k] = run;
            run += local[k];
            g_cnt[base + k] = 0;     // reset for next call's count
            g_fill[base + k] = 0;    // reset for this call's scatter
        }
        if (t == 999) g_rowptr[Vn] = run;
    }
}

__global__ void scatter_kernel(const int* __restrict__ rows,
                               const int* __restrict__ cols,
                               const float* __restrict__ vals) {
    int j = blockIdx.x * blockDim.x + threadIdx.x;
    if (j < NNZn) {
        int r = rows[j];
        int p = g_rowptr[r] + atomicAdd(&g_fill[r], 1);
        __half2 h2 = __half2half2(__float2half_rn(vals[j]));
        g_ev[p] = make_int2(cols[j] << 8, *reinterpret_cast<int*>(&h2));  // uint4 row index (256/row)
    }
}

// ---------------- SpMM (CSR gather), fp16 rows, LDG.128 gathers, half2 staging (R6 config) ----------------
__device__ __forceinline__ void hacc4(__half2* st, const uint4& r, __half2 w2) {
    const __half2* h = reinterpret_cast<const __half2*>(&r);
    st[0] = __hfma2(w2, h[0], st[0]);
    st[1] = __hfma2(w2, h[1], st[1]);
    st[2] = __hfma2(w2, h[2], st[2]);
    st[3] = __hfma2(w2, h[3], st[3]);
}

__device__ __forceinline__ void flush_st(float* acc, __half2* st) {
#pragma unroll
    for (int q = 0; q < 4; q++) {
        float2 fv = __half22float2(st[q]);
        acc[2 * q]     += fv.x;
        acc[2 * q + 1] += fv.y;
        st[q] = __half2half2(__ushort_as_half(0));
    }
}

__device__ __forceinline__ __half2 evw(const int2& ev) {
    return *reinterpret_cast<const __half2*>(&ev.y);
}

// grid: (Vn, 2), block: 128 threads, each thread one uint4 = 8 halves
template <int MODE>  // 0: xk = L*y ; 1: xk = 2*L*y - xm2
__global__ void __launch_bounds__(128, 9) spmm_kernel(int iy, int im2, int io) {
    const unsigned term = (unsigned)Vn * 256;   // uint4 per term
    const uint4* __restrict__ y4 = reinterpret_cast<const uint4*>(g_xh) + (size_t)iy  * term;
    const uint4* __restrict__ m4 = reinterpret_cast<const uint4*>(g_xh) + (size_t)im2 * term;
    uint4* __restrict__       o4 = reinterpret_cast<uint4*>(g_xh) + (size_t)io * term;

    int v = blockIdx.x;
    unsigned f = blockIdx.y * 128 + threadIdx.x;   // uint4 index 0..255 within the row
    int s = g_rowptr[v], e = g_rowptr[v + 1];

    float acc[8];
#pragma unroll
    for (int q = 0; q < 8; q++) acc[q] = 0.f;
    __half2 st[4];
#pragma unroll
    for (int q = 0; q < 4; q++) st[q] = __half2half2(__ushort_as_half(0));

    int j = s;
    for (; j + 7 < e; j += 8) {
        int2 ev0 = __ldg(&g_ev[j]);
        int2 ev1 = __ldg(&g_ev[j + 1]);
        int2 ev2 = __ldg(&g_ev[j + 2]);
        int2 ev3 = __ldg(&g_ev[j + 3]);
        int2 ev4 = __ldg(&g_ev[j + 4]);
        int2 ev5 = __ldg(&g_ev[j + 5]);
        int2 ev6 = __ldg(&g_ev[j + 6]);
        int2 ev7 = __ldg(&g_ev[j + 7]);
        {
            uint4 r0 = __ldg(&y4[(unsigned)ev0.x + f]);
            uint4 r1 = __ldg(&y4[(unsigned)ev1.x + f]);
            uint4 r2 = __ldg(&y4[(unsigned)ev2.x + f]);
            uint4 r3 = __ldg(&y4[(unsigned)ev3.x + f]);
            hacc4(st, r0, evw(ev0));
            hacc4(st, r1, evw(ev1));
            hacc4(st, r2, evw(ev2));
            hacc4(st, r3, evw(ev3));
        }
        {
            uint4 r0 = __ldg(&y4[(unsigned)ev4.x + f]);
            uint4 r1 = __ldg(&y4[(unsigned)ev5.x + f]);
            uint4 r2 = __ldg(&y4[(unsigned)ev6.x + f]);
            uint4 r3 = __ldg(&y4[(unsigned)ev7.x + f]);
            hacc4(st, r0, evw(ev4));
            hacc4(st, r1, evw(ev5));
            hacc4(st, r2, evw(ev6));
            hacc4(st, r3, evw(ev7));
        }
        flush_st(acc, st);
    }
    for (; j < e; j++) {
        int2 ev = __ldg(&g_ev[j]);
        uint4 r0 = __ldg(&y4[(unsigned)ev.x + f]);
        hacc4(st, r0, evw(ev));
    }
    flush_st(acc, st);

    size_t oi = (size_t)v * 256 + f;
    if (MODE == 1) {
        uint4 mraw = __ldcs(&m4[oi]);
        const __half2* mh = reinterpret_cast<const __half2*>(&mraw);
#pragma unroll
        for (int q = 0; q < 4; q++) {
            float2 m = __half22float2(mh[q]);
            acc[2 * q]     = 2.f * acc[2 * q]     - m.x;
            acc[2 * q + 1] = 2.f * acc[2 * q + 1] - m.y;
        }
    }
    uint4 outv;
    __half2* oh = reinterpret_cast<__half2*>(&outv);
#pragma unroll
    for (int q = 0; q < 4; q++)
        oh[q] = __floats2half2_rn(acc[2 * q], acc[2 * q + 1]);
    __stcs(&o4[oi], outv);
}

// ---------------- fused fp16 GEMM, cp.async double-buffered + ldmatrix fragments ----------------
// out(b,o,v) = sum_{r,i} xs[r][v][b*128+i] * W[r][i][o] + bias[o]
#define MMA_F16(C, A, Bf)                                                                   \
    asm volatile("mma.sync.aligned.m16n8k16.row.col.f32.f16.f16.f32 "                      \
                 "{%0,%1,%2,%3},{%4,%5,%6,%7},{%8,%9},{%0,%1,%2,%3};"                       \
                 : "+f"((C)[0]), "+f"((C)[1]), "+f"((C)[2]), "+f"((C)[3])                   \
                 : "r"((A)[0]), "r"((A)[1]), "r"((A)[2]), "r"((A)[3]),                      \
                   "r"((Bf)[0]), "r"((Bf)[1]))

#define CP_ASYNC16(dst, src) \
    asm volatile("cp.async.cg.shared.global [%0], [%1], 16;" :: "r"(dst), "l"(src))
#define CP_COMMIT() asm volatile("cp.async.commit_group;")
#define CP_WAIT1()  asm volatile("cp.async.wait_group 1;")
#define CP_WAIT0()  asm volatile("cp.async.wait_group 0;")

#define LDSM_X4(r0, r1, r2, r3, addr) \
    asm volatile("ldmatrix.sync.aligned.m8n8.x4.shared.b16 {%0,%1,%2,%3}, [%4];" \
                 : "=r"(r0), "=r"(r1), "=r"(r2), "=r"(r3) : "r"(addr))
#define LDSM_X2(r0, r1, addr) \
    asm volatile("ldmatrix.sync.aligned.m8n8.x2.shared.b16 {%0,%1}, [%2];" \
                 : "=r"(r0), "=r"(r1) : "r"(addr))

// block tile: M=128 (v), N=128 (o), K=512 in 16 chunks of 32 halves, 2-stage cp.async pipeline.
// 256 threads = 8 warps (2 x 4). Tile stride 20 u32 = 80 B (16B-aligned; ldmatrix conflict-free:
// 8 row starts mod 32 banks = {0,20,8,28,16,4,24,12} — disjoint 4-bank spans).
// Pool: 2 tensors x 2 buffers x 128x20 u32 = 10240 u32 = 40 KB; Cs [128][65] aliased.
__global__ void __launch_bounds__(256) gemm_kernel(const float* __restrict__ bias,
                                                   float* __restrict__ out) {
    __shared__ __align__(16) unsigned pool[10240];  // 40 KB
    unsigned* As = pool;                            // [2][128][20]
    unsigned* Ws = pool + 5120;                     // [2][128][20]
    float*    Cs = reinterpret_cast<float*>(pool);  // [128][65] (aliased after compute)

    int tid  = threadIdx.x;
    int lane = tid & 31;
    int warp = tid >> 5;
    int wm   = warp & 1;
    int wn   = warp >> 1;  // 0..3 : 32 o-cols each
    int bb   = blockIdx.y;
    int v0   = blockIdx.x * 128;
    int t    = lane & 3;
    int g    = lane >> 2;

    // per-lane ldmatrix base addresses (bytes, shared space)
    uint32_t smem_base = (uint32_t)__cvta_generic_to_shared(pool);
    uint32_t Asm = smem_base;               // A buffers (buf stride 10240 B)
    uint32_t Wsm = smem_base + 5120u * 4u;  // W buffers
    // A x4: lanes 0-7 rows+0..7/k-lo, 8-15 rows+8..15/k-lo, 16-23 rows/k-hi, 24-31 rows+8/k-hi
    uint32_t a_lane = ((uint32_t)(wm * 16 + (lane & 15)) * 20u + ((lane >> 4) << 2)) * 4u;
    // W x2: lanes 0-7 n-rows o0..o0+7 / k-lo, lanes 8-15 same rows / k-hi
    uint32_t b_lane = ((uint32_t)(wn * 32 + (lane & 7)) * 20u + (((lane >> 3) & 1) << 2)) * 4u;

    float c[4][4][4];
#pragma unroll
    for (int nt = 0; nt < 4; nt++) {
        int o = wn * 32 + nt * 8 + t * 2;
        float b0 = bias[o], b1 = bias[o + 1];
#pragma unroll
        for (int mt = 0; mt < 4; mt++) {
            c[mt][nt][0] = b0; c[mt][nt][1] = b1;
            c[mt][nt][2] = b0; c[mt][nt][3] = b1;
        }
    }

    // stage issue: A rows clamp to row 0 when v >= Vn (finite garbage, never stored)
    auto issue = [&](int stg) {
        int buf = stg & 1;
        int r   = stg >> 2;          // term index (4 chunks of 32 per 128-wide term)
        int i0  = (stg & 3) * 32;    // offset within term's 128 features
#pragma unroll
        for (int p = 0; p < 2; p++) {
            int idx = tid + p * 256;      // 0..511
            int row = idx >> 2;
            int seg = idx & 3;
            int v   = v0 + row;
            int vc  = v < Vn ? v : 0;
            const __half* src = g_xh + (size_t)(r * Vn + vc) * Fn + bb * 128 + i0 + seg * 8;
            unsigned dst = (unsigned)__cvta_generic_to_shared(As + buf * 2560 + row * 20 + seg * 4);
            CP_ASYNC16(dst, src);
        }
#pragma unroll
        for (int p = 0; p < 2; p++) {
            int idx = tid + p * 256;
            int o   = idx >> 2;
            int seg = idx & 3;
            const __half* src = g_wt + (size_t)o * 512 + stg * 32 + seg * 8;
            unsigned dst = (unsigned)__cvta_generic_to_shared(Ws + buf * 2560 + o * 20 + seg * 4);
            CP_ASYNC16(dst, src);
        }
        CP_COMMIT();
    };

    issue(0);
    for (int stg = 0; stg < 16; stg++) {
        if (stg + 1 < 16) {
            issue(stg + 1);
            CP_WAIT1();
        } else {
            CP_WAIT0();
        }
        __syncthreads();
        int buf = stg & 1;
        uint32_t Ab = Asm + (uint32_t)buf * 10240u + a_lane;
        uint32_t Wb = Wsm + (uint32_t)buf * 10240u + b_lane;
#pragma unroll
        for (int s = 0; s < 2; s++) {           // 2 k-steps of 16 halves
            unsigned bf[4][2];
#pragma unroll
            for (int nt = 0; nt < 4; nt++)
                LDSM_X2(bf[nt][0], bf[nt][1], Wb + nt * 640u + s * 32u);
#pragma unroll
            for (int mt = 0; mt < 4; mt++) {
                unsigned a[4];
                LDSM_X4(a[0], a[1], a[2], a[3], Ab + mt * 2560u + s * 32u);
#pragma unroll
                for (int nt = 0; nt < 4; nt++)
                    MMA_F16(c[mt][nt], a, bf[nt]);
            }
        }
        __syncthreads();
    }

    // stage C into shared as [o][v] for coalesced (B,Cout,V) stores — two passes of 64 rows
#pragma unroll
    for (int p = 0; p < 2; p++) {
#pragma unroll
        for (int mth = 0; mth < 2; mth++) {
            int mt = 2 * p + mth;
#pragma unroll
            for (int nt = 0; nt < 4; nt++) {
                int vr = mth * 32 + wm * 16 + g;     // 0..63 within pass
                int o  = wn * 32 + nt * 8 + t * 2;
                Cs[o * 65 + vr]           = c[mt][nt][0];
                Cs[(o + 1) * 65 + vr]     = c[mt][nt][1];
                Cs[o * 65 + vr + 8]       = c[mt][nt][2];
                Cs[(o + 1) * 65 + vr + 8] = c[mt][nt][3];
            }
        }
        __syncthreads();
        for (int idx = tid; idx < 128 * 64; idx += 256) {
            int o  = idx >> 6;
            int vl = idx & 63;
            int v  = v0 + p * 64 + vl;
            if (v < Vn)
                __stcs(&out[((size_t)bb * 128 + o) * Vn + v], Cs[o * 65 + vl]);
        }
        __syncthreads();
    }
}

// ---------------- launch (serial R10 structure — nothing co-runs with the SpMM chain) ----------------
extern "C" void kernel_launch(void* const* d_in, const int* in_sizes, int n_in,
                              void* d_out, int out_size) {
    const float* x        = (const float*)d_in[0];
    const float* weight   = (const float*)d_in[1];
    const float* bias     = (const float*)d_in[2];
    const float* lap_vals = (const float*)d_in[3];
    const int*   lap_rows = (const int*)d_in[4];
    const int*   lap_cols = (const int*)d_in[5];
    float* out = (float*)d_out;

    // prelude: fused {count | transpose | wprep}, scan (also resets counters), scatter
    fused_prelude_kernel<<<COUNT_BLKS + TRANS_BLKS + WPREP_BLKS, 256>>>(lap_rows, x, weight);
    scan_kernel<<<1, 1024>>>();
    scatter_kernel<<<NNZn / 256, 256>>>(lap_rows, lap_cols, lap_vals);

    // Chebyshev recursion: x1 = L x0 ; x2 = 2 L x1 - x0 ; x3 = 2 L x2 - x1
    spmm_kernel<0><<<dim3(Vn, 2), 128>>>(0, 0, 1);
    spmm_kernel<1><<<dim3(Vn, 2), 128>>>(1, 0, 2);
    spmm_kernel<1><<<dim3(Vn, 2), 128>>>(2, 1, 3);

    // fused fp16 GEMM over all 4 terms + bias, writes (B, Cout, V)
    gemm_kernel<<<dim3((Vn + 127) / 128, Bn), 256>>>(bias, out);
}

// round 16
// speedup vs baseline: 1.4169x; 1.0075x over previous
#include <cuda_runtime.h>
#include <cuda_fp16.h>
#include <cstdint>

#define Vn   20000
#define NNZn 640000
#define Bn   16
#define CINn 128
#define COUTn 128
#define Rn   4
#define Fn   2048   // Bn * CINn

// ---------------- scratch (static device memory; no allocation at runtime) ----------------
__device__ __half g_xh[(size_t)Rn * Vn * Fn];   // 4 Chebyshev terms, each (V, 2048) fp16 (~327 MB)
__device__ unsigned g_wtf[32768];               // W in mma-B fragment order: [stg][wn][lane][16 u32] = 128 KB
__device__ int    g_rowptr[Vn + 1];
__device__ int    g_cnt[Vn];                    // zeroed statically; re-zeroed by scan_kernel each call
__device__ int    g_fill[Vn];                   // zeroed statically; re-zeroed by scan_kernel each call
__device__ int2   g_ev[NNZn];                   // packed: {col*256 (uint4 row idx), half2(w,w) bits}

// ---------------- fused prelude: count | transpose | wfrag (independent work) ----------------
#define COUNT_BLKS 2500
#define TRANS_BLKS 40000     // (Vn/32) * (Fn/32) = 625 * 64
#define WPREP_BLKS 128       // 32768 u32, one per thread
__global__ void __launch_bounds__(256) fused_prelude_kernel(const int* __restrict__ rows,
                                                            const float* __restrict__ x,
                                                            const float* __restrict__ weight) {
    __shared__ float tile[32][33];
    int bid = blockIdx.x;
    int tid = threadIdx.x;
    if (bid < COUNT_BLKS) {
        int j = bid * 256 + tid;
        if (j < NNZn) atomicAdd(&g_cnt[rows[j]], 1);
    } else if (bid < COUNT_BLKS + TRANS_BLKS) {
        int b2 = bid - COUNT_BLKS;
        int v0 = (b2 % 625) * 32;
        int c0 = (b2 / 625) * 32;
        int tx = tid & 31;
        int ty0 = tid >> 5;          // 0..7
#pragma unroll
        for (int q = 0; q < 4; q++) {
            int ty = ty0 + q * 8;
            tile[ty][tx] = x[(size_t)(c0 + ty) * Vn + (v0 + tx)];
        }
        __syncthreads();
#pragma unroll
        for (int q = 0; q < 4; q++) {
            int ty = ty0 + q * 8;
            g_xh[(size_t)(v0 + ty) * Fn + (c0 + tx)] = __float2half_rn(tile[tx][ty]);
        }
    } else {
        // W fragment pack: idx -> (stg, wn, lane, q); q = s*8 + nt*2 + j
        // u32 = halves { weight[k][o], weight[k+1][o] },
        //   o = wn*32 + nt*8 + (lane>>2),  k = stg*32 + s*16 + j*8 + (lane&3)*2
        int idx = (bid - COUNT_BLKS - TRANS_BLKS) * 256 + tid;   // 0..32767
        int q    = idx & 15;
        int l    = (idx >> 4) & 31;
        int wn   = (idx >> 9) & 3;
        int stg  = idx >> 11;
        int s    = q >> 3;
        int nt   = (q >> 1) & 3;
        int j    = q & 1;
        int o    = wn * 32 + nt * 8 + (l >> 2);
        int k    = stg * 32 + s * 16 + j * 8 + (l & 3) * 2;
        __half2 hv = __floats2half2_rn(weight[(size_t)k * 128 + o],
                                       weight[(size_t)(k + 1) * 128 + o]);
        g_wtf[idx] = *reinterpret_cast<unsigned*>(&hv);
    }
}

// ---------------- exclusive scan over 20000 counters (2 barriers), also resets cnt/fill ----------------
__global__ void __launch_bounds__(1024) scan_kernel() {
    __shared__ int wsum[32];
    int t = threadIdx.x;          // 0..1023; threads 0..999 each own 20 rows
    int local[20];
    int s = 0;
    if (t < 1000) {
        int base = t * 20;
#pragma unroll
        for (int k = 0; k < 20; k++) {
            local[k] = g_cnt[base + k];
            s += local[k];
        }
    }
    int lane = t & 31, w = t >> 5;
    int ps = s;
#pragma unroll
    for (int off = 1; off < 32; off <<= 1) {
        int o = __shfl_up_sync(0xffffffff, ps, off);
        if (lane >= off) ps += o;
    }
    if (lane == 31) wsum[w] = ps;
    __syncthreads();
    if (w == 0) {
        int v = wsum[lane];
        int pv = v;
#pragma unroll
        for (int off = 1; off < 32; off <<= 1) {
            int o = __shfl_up_sync(0xffffffff, pv, off);
            if (lane >= off) pv += o;
        }
        wsum[lane] = pv - v;   // exclusive warp offsets
    }
    __syncthreads();
    int excl = wsum[w] + ps - s;   // exclusive prefix for this thread
    if (t < 1000) {
        int base = t * 20;
        int run = excl;
#pragma unroll
        for (int k = 0; k < 20; k++) {
            g_rowptr[base + k] = run;
            run += local[k];
            g_cnt[base + k] = 0;     // reset for next call's count
            g_fill[base + k] = 0;    // reset for this call's scatter
        }
        if (t == 999) g_rowptr[Vn] = run;
    }
}

__global__ void scatter_kernel(const int* __restrict__ rows,
                               const int* __restrict__ cols,
                               const float* __restrict__ vals) {
    int j = blockIdx.x * blockDim.x + threadIdx.x;
    if (j < NNZn) {
        int r = rows[j];
        int p = g_rowptr[r] + atomicAdd(&g_fill[r], 1);
        __half2 h2 = __half2half2(__float2half_rn(vals[j]));
        g_ev[p] = make_int2(cols[j] << 8, *reinterpret_cast<int*>(&h2));  // uint4 row index (256/row)
    }
}

// ---------------- SpMM (CSR gather), fp16 rows, LDG.128 gathers, half2 staging (R6 config) ----------------
__device__ __forceinline__ void hacc4(__half2* st, const uint4& r, __half2 w2) {
    const __half2* h = reinterpret_cast<const __half2*>(&r);
    st[0] = __hfma2(w2, h[0], st[0]);
    st[1] = __hfma2(w2, h[1], st[1]);
    st[2] = __hfma2(w2, h[2], st[2]);
    st[3] = __hfma2(w2, h[3], st[3]);
}

__device__ __forceinline__ void flush_st(float* acc, __half2* st) {
#pragma unroll
    for (int q = 0; q < 4; q++) {
        float2 fv = __half22float2(st[q]);
        acc[2 * q]     += fv.x;
        acc[2 * q + 1] += fv.y;
        st[q] = __half2half2(__ushort_as_half(0));
    }
}

__device__ __forceinline__ __half2 evw(const int2& ev) {
    return *reinterpret_cast<const __half2*>(&ev.y);
}

// grid: (Vn, 2), block: 128 threads, each thread one uint4 = 8 halves
template <int MODE>  // 0: xk = L*y ; 1: xk = 2*L*y - xm2
__global__ void __launch_bounds__(128, 9) spmm_kernel(int iy, int im2, int io) {
    const unsigned term = (unsigned)Vn * 256;   // uint4 per term
    const uint4* __restrict__ y4 = reinterpret_cast<const uint4*>(g_xh) + (size_t)iy  * term;
    const uint4* __restrict__ m4 = reinterpret_cast<const uint4*>(g_xh) + (size_t)im2 * term;
    uint4* __restrict__       o4 = reinterpret_cast<uint4*>(g_xh) + (size_t)io * term;

    int v = blockIdx.x;
    unsigned f = blockIdx.y * 128 + threadIdx.x;   // uint4 index 0..255 within the row
    int s = g_rowptr[v], e = g_rowptr[v + 1];

    float acc[8];
#pragma unroll
    for (int q = 0; q < 8; q++) acc[q] = 0.f;
    __half2 st[4];
#pragma unroll
    for (int q = 0; q < 4; q++) st[q] = __half2half2(__ushort_as_half(0));

    int j = s;
    for (; j + 7 < e; j += 8) {
        int2 ev0 = __ldg(&g_ev[j]);
        int2 ev1 = __ldg(&g_ev[j + 1]);
        int2 ev2 = __ldg(&g_ev[j + 2]);
        int2 ev3 = __ldg(&g_ev[j + 3]);
        int2 ev4 = __ldg(&g_ev[j + 4]);
        int2 ev5 = __ldg(&g_ev[j + 5]);
        int2 ev6 = __ldg(&g_ev[j + 6]);
        int2 ev7 = __ldg(&g_ev[j + 7]);
        {
            uint4 r0 = __ldg(&y4[(unsigned)ev0.x + f]);
            uint4 r1 = __ldg(&y4[(unsigned)ev1.x + f]);
            uint4 r2 = __ldg(&y4[(unsigned)ev2.x + f]);
            uint4 r3 = __ldg(&y4[(unsigned)ev3.x + f]);
            hacc4(st, r0, evw(ev0));
            hacc4(st, r1, evw(ev1));
            hacc4(st, r2, evw(ev2));
            hacc4(st, r3, evw(ev3));
        }
        {
            uint4 r0 = __ldg(&y4[(unsigned)ev4.x + f]);
            uint4 r1 = __ldg(&y4[(unsigned)ev5.x + f]);
            uint4 r2 = __ldg(&y4[(unsigned)ev6.x + f]);
            uint4 r3 = __ldg(&y4[(unsigned)ev7.x + f]);
            hacc4(st, r0, evw(ev4));
            hacc4(st, r1, evw(ev5));
            hacc4(st, r2, evw(ev6));
            hacc4(st, r3, evw(ev7));
        }
        flush_st(acc, st);
    }
    for (; j < e; j++) {
        int2 ev = __ldg(&g_ev[j]);
        uint4 r0 = __ldg(&y4[(unsigned)ev.x + f]);
        hacc4(st, r0, evw(ev));
    }
    flush_st(acc, st);

    size_t oi = (size_t)v * 256 + f;
    if (MODE == 1) {
        uint4 mraw = __ldcs(&m4[oi]);
        const __half2* mh = reinterpret_cast<const __half2*>(&mraw);
#pragma unroll
        for (int q = 0; q < 4; q++) {
            float2 m = __half22float2(mh[q]);
            acc[2 * q]     = 2.f * acc[2 * q]     - m.x;
            acc[2 * q + 1] = 2.f * acc[2 * q + 1] - m.y;
        }
    }
    uint4 outv;
    __half2* oh = reinterpret_cast<__half2*>(&outv);
#pragma unroll
    for (int q = 0; q < 4; q++)
        oh[q] = __floats2half2_rn(acc[2 * q], acc[2 * q + 1]);
    __stcs(&o4[oi], outv);
}

// ---------------- fused fp16 GEMM: A via cp.async smem + ldmatrix, W via fragment LDG, direct stores ----------------
// out(b,o,v) = sum_{r,i} xs[r][v][b*128+i] * W[r][i][o] + bias[o]
#define MMA_F16(C, A, Bf)                                                                   \
    asm volatile("mma.sync.aligned.m16n8k16.row.col.f32.f16.f16.f32 "                      \
                 "{%0,%1,%2,%3},{%4,%5,%6,%7},{%8,%9},{%0,%1,%2,%3};"                       \
                 : "+f"((C)[0]), "+f"((C)[1]), "+f"((C)[2]), "+f"((C)[3])                   \
                 : "r"((A)[0]), "r"((A)[1]), "r"((A)[2]), "r"((A)[3]),                      \
                   "r"((Bf)[0]), "r"((Bf)[1]))

#define CP_ASYNC16(dst, src) \
    asm volatile("cp.async.cg.shared.global [%0], [%1], 16;" :: "r"(dst), "l"(src))
#define CP_COMMIT() asm volatile("cp.async.commit_group;")
#define CP_WAIT1()  asm volatile("cp.async.wait_group 1;")
#define CP_WAIT0()  asm volatile("cp.async.wait_group 0;")

#define LDSM_X4(r0, r1, r2, r3, addr) \
    asm volatile("ldmatrix.sync.aligned.m8n8.x4.shared.b16 {%0,%1,%2,%3}, [%4];" \
                 : "=r"(r0), "=r"(r1), "=r"(r2), "=r"(r3) : "r"(addr))

// block tile: M=128 (v), N=128 (o), K=512 in 16 chunks of 32 halves, 2-stage cp.async pipeline (A only).
// 256 threads = 8 warps (2 x 4). A stride 20 u32 (16B-aligned, ldmatrix conflict-free). Smem 20 KB.
// W fragments from g_wtf (L2-hot 128 KB), C stored directly (full 32B sectors per 8-lane group).
__global__ void __launch_bounds__(256) gemm_kernel(const float* __restrict__ bias,
                                                   float* __restrict__ out) {
    __shared__ __align__(16) unsigned As[5120];     // [2][128][20] = 20 KB

    int tid  = threadIdx.x;
    int lane = tid & 31;
    int warp = tid >> 5;
    int wm   = warp & 1;
    int wn   = warp >> 1;  // 0..3 : 32 o-cols each
    int bb   = blockIdx.y;
    int v0   = blockIdx.x * 128;
    int t    = lane & 3;
    int g    = lane >> 2;

    uint32_t Asm = (uint32_t)__cvta_generic_to_shared(As);
    // A x4 ldmatrix lane address: lanes 0-15 rows wm*16+0..15 (k-lo), 16-31 same rows (k-hi)
    uint32_t a_lane = ((uint32_t)(wm * 16 + (lane & 15)) * 20u + ((lane >> 4) << 2)) * 4u;
    // W fragment base for this warp+lane: [stg][wn][lane][16 u32]
    const uint4* wf = reinterpret_cast<const uint4*>(g_wtf) + ((size_t)wn * 32 + lane) * 4;

    float c[4][4][4];
#pragma unroll
    for (int nt = 0; nt < 4; nt++) {
        int o = wn * 32 + nt * 8 + t * 2;
        float b0 = bias[o], b1 = bias[o + 1];
#pragma unroll
        for (int mt = 0; mt < 4; mt++) {
            c[mt][nt][0] = b0; c[mt][nt][1] = b1;
            c[mt][nt][2] = b0; c[mt][nt][3] = b1;
        }
    }

    // stage issue: A rows clamp to row 0 when v >= Vn (finite garbage, never stored)
    auto issue = [&](int stg) {
        int buf = stg & 1;
        int r   = stg >> 2;          // term index (4 chunks of 32 per 128-wide term)
        int i0  = (stg & 3) * 32;    // offset within term's 128 features
#pragma unroll
        for (int p = 0; p < 2; p++) {
            int idx = tid + p * 256;      // 0..511
            int row = idx >> 2;
            int seg = idx & 3;
            int v   = v0 + row;
            int vc  = v < Vn ? v : 0;
            const __half* src = g_xh + (size_t)(r * Vn + vc) * Fn + bb * 128 + i0 + seg * 8;
            unsigned dst = (unsigned)__cvta_generic_to_shared(As + buf * 2560 + row * 20 + seg * 4);
            CP_ASYNC16(dst, src);
        }
        CP_COMMIT();
    };

    issue(0);
    for (int stg = 0; stg < 16; stg++) {
        // W fragments for this stage: 4 coalesced LDG.128 from L2-hot g_wtf,
        // landing in ONE contiguous array (stage stride = 4*32*16 u32 = 512 uint4)
        uint4 w[4];
#pragma unroll
        for (int p = 0; p < 4; p++)
            w[p] = __ldg(&wf[(size_t)stg * 512 + p]);
        const unsigned* w_u = reinterpret_cast<const unsigned*>(w);

        if (stg + 1 < 16) {
            issue(stg + 1);
            CP_WAIT1();
        } else {
            CP_WAIT0();
        }
        __syncthreads();
        int buf = stg & 1;
        uint32_t Ab = Asm + (uint32_t)buf * 10240u + a_lane;
#pragma unroll
        for (int s = 0; s < 2; s++) {           // 2 k-steps of 16 halves
            // fragment order within the 8 u32 of step s: nt0{j0,j1}, nt1{j0,j1}, nt2.., nt3..
            const unsigned* q = w_u + s * 8;
            unsigned bf[4][2];
#pragma unroll
            for (int nt = 0; nt < 4; nt++) {
                bf[nt][0] = q[nt * 2];
                bf[nt][1] = q[nt * 2 + 1];
            }
#pragma unroll
            for (int mt = 0; mt < 4; mt++) {
                unsigned a[4];
                LDSM_X4(a[0], a[1], a[2], a[3], Ab + mt * 2560u + s * 32u);
#pragma unroll
                for (int nt = 0; nt < 4; nt++)
                    MMA_F16(c[mt][nt], a, bf[nt]);
            }
        }
        __syncthreads();
    }

    // direct stores: lanes with equal (lane&3) cover 8 consecutive v -> full 32B sectors
#pragma unroll
    for (int mt = 0; mt < 4; mt++) {
        int vr = v0 + mt * 32 + wm * 16 + g;
#pragma unroll
        for (int nt = 0; nt < 4; nt++) {
            int o = wn * 32 + nt * 8 + t * 2;
            size_t b0 = ((size_t)bb * 128 + o) * Vn;
            size_t b1 = ((size_t)bb * 128 + o + 1) * Vn;
            if (vr < Vn) {
                __stcs(&out[b0 + vr], c[mt][nt][0]);
                __stcs(&out[b1 + vr], c[mt][nt][1]);
            }
            if (vr + 8 < Vn) {
                __stcs(&out[b0 + vr + 8], c[mt][nt][2]);
                __stcs(&out[b1 + vr + 8], c[mt][nt][3]);
            }
        }
    }
}

// ---------------- launch (serial — nothing co-runs with the SpMM chain) ----------------
extern "C" void kernel_launch(void* const* d_in, const int* in_sizes, int n_in,
                              void* d_out, int out_size) {
    const float* x        = (const float*)d_in[0];
    const float* weight   = (const float*)d_in[1];
    const float* bias     = (const float*)d_in[2];
    const float* lap_vals = (const float*)d_in[3];
    const int*   lap_rows = (const int*)d_in[4];
    const int*   lap_cols = (const int*)d_in[5];
    float* out = (float*)d_out;

    // prelude: fused {count | transpose | wfrag}, scan (also resets counters), scatter
    fused_prelude_kernel<<<COUNT_BLKS + TRANS_BLKS + WPREP_BLKS, 256>>>(lap_rows, x, weight);
    scan_kernel<<<1, 1024>>>();
    scatter_kernel<<<NNZn / 256, 256>>>(lap_rows, lap_cols, lap_vals);

    // Chebyshev recursion: x1 = L x0 ; x2 = 2 L x1 - x0 ; x3 = 2 L x2 - x1
    spmm_kernel<0><<<dim3(Vn, 2), 128>>>(0, 0, 1);
    spmm_kernel<1><<<dim3(Vn, 2), 128>>>(1, 0, 2);
    spmm_kernel<1><<<dim3(Vn, 2), 128>>>(2, 1, 3);

    // fused fp16 GEMM over all 4 terms + bias, writes (B, Cout, V)
    gemm_kernel<<<dim3((Vn + 127) / 128, Bn), 256>>>(bias, out);
}

// round 17
// speedup vs baseline: 1.4300x; 1.0092x over previous
#include <cuda_runtime.h>
#include <cuda_fp16.h>
#include <cstdint>

#define Vn   20000
#define NNZn 640000
#define Bn   16
#define CINn 128
#define COUTn 128
#define Rn   4
#define Fn   2048   // Bn * CINn

// ---------------- scratch (static device memory; no allocation at runtime) ----------------
__device__ __half g_xh[(size_t)Rn * Vn * Fn];   // 4 power-basis terms y_k, each (V, 2048) fp16
__device__ unsigned g_wtf[32768];               // W' in mma-B fragment order: [stg][wn][lane][16 u32] = 128 KB
__device__ int    g_rowptr[Vn + 1];
__device__ int    g_cnt[Vn];                    // zeroed statically; re-zeroed by scan_kernel each call
__device__ int    g_fill[Vn];                   // zeroed statically; re-zeroed by scan_kernel each call
__device__ int2   g_ev[NNZn];                   // packed: {col*256 (uint4 row idx), half2(w,w) bits}

// ---------------- fused prelude: count | transpose | wfrag (independent work) ----------------
#define COUNT_BLKS 2500
#define TRANS_BLKS 40000     // (Vn/32) * (Fn/32) = 625 * 64
#define WPREP_BLKS 128       // 32768 u32, one per thread
__global__ void __launch_bounds__(256) fused_prelude_kernel(const int* __restrict__ rows,
                                                            const float* __restrict__ x,
                                                            const float* __restrict__ weight) {
    __shared__ float tile[32][33];
    int bid = blockIdx.x;
    int tid = threadIdx.x;
    if (bid < COUNT_BLKS) {
        int j = bid * 256 + tid;
        if (j < NNZn) atomicAdd(&g_cnt[rows[j]], 1);
    } else if (bid < COUNT_BLKS + TRANS_BLKS) {
        int b2 = bid - COUNT_BLKS;
        int v0 = (b2 % 625) * 32;
        int c0 = (b2 / 625) * 32;
        int tx = tid & 31;
        int ty0 = tid >> 5;          // 0..7
#pragma unroll
        for (int q = 0; q < 4; q++) {
            int ty = ty0 + q * 8;
            tile[ty][tx] = x[(size_t)(c0 + ty) * Vn + (v0 + tx)];
        }
        __syncthreads();
#pragma unroll
        for (int q = 0; q < 4; q++) {
            int ty = ty0 + q * 8;
            g_xh[(size_t)(v0 + ty) * Fn + (c0 + tx)] = __float2half_rn(tile[tx][ty]);
        }
    } else {
        // W' fragment pack (Chebyshev->power basis folded into weights):
        //   W'0 = W0 - W2 ; W'1 = W1 - 3 W3 ; W'2 = 2 W2 ; W'3 = 4 W3
        // idx -> (stg, wn, lane, q); q = s*8 + nt*2 + j
        // u32 = halves { W'[k][o], W'[k+1][o] },
        //   o = wn*32 + nt*8 + (lane>>2),  k = stg*32 + s*16 + j*8 + (lane&3)*2
        int idx = (bid - COUNT_BLKS - TRANS_BLKS) * 256 + tid;   // 0..32767
        int q    = idx & 15;
        int l    = (idx >> 4) & 31;
        int wn   = (idx >> 9) & 3;
        int stg  = idx >> 11;
        int s    = q >> 3;
        int nt   = (q >> 1) & 3;
        int j    = q & 1;
        int o    = wn * 32 + nt * 8 + (l >> 2);
        int k    = stg * 32 + s * 16 + j * 8 + (l & 3) * 2;
        float w0, w1;
#pragma unroll
        for (int e = 0; e < 2; e++) {
            int kk = k + e;
            int r  = kk >> 7;          // power-basis term index
            int i  = kk & 127;
            float wv;
            if (r == 0)
                wv = weight[(size_t)(0 * 128 + i) * 128 + o] - weight[(size_t)(2 * 128 + i) * 128 + o];
            else if (r == 1)
                wv = weight[(size_t)(1 * 128 + i) * 128 + o] - 3.f * weight[(size_t)(3 * 128 + i) * 128 + o];
            else if (r == 2)
                wv = 2.f * weight[(size_t)(2 * 128 + i) * 128 + o];
            else
                wv = 4.f * weight[(size_t)(3 * 128 + i) * 128 + o];
            if (e == 0) w0 = wv; else w1 = wv;
        }
        __half2 hv = __floats2half2_rn(w0, w1);
        g_wtf[idx] = *reinterpret_cast<unsigned*>(&hv);
    }
}

// ---------------- exclusive scan over 20000 counters (2 barriers), also resets cnt/fill ----------------
__global__ void __launch_bounds__(1024) scan_kernel() {
    __shared__ int wsum[32];
    int t = threadIdx.x;          // 0..1023; threads 0..999 each own 20 rows
    int local[20];
    int s = 0;
    if (t < 1000) {
        int base = t * 20;
#pragma unroll
        for (int k = 0; k < 20; k++) {
            local[k] = g_cnt[base + k];
            s += local[k];
        }
    }
    int lane = t & 31, w = t >> 5;
    int ps = s;
#pragma unroll
    for (int off = 1; off < 32; off <<= 1) {
        int o = __shfl_up_sync(0xffffffff, ps, off);
        if (lane >= off) ps += o;
    }
    if (lane == 31) wsum[w] = ps;
    __syncthreads();
    if (w == 0) {
        int v = wsum[lane];
        int pv = v;
#pragma unroll
        for (int off = 1; off < 32; off <<= 1) {
            int o = __shfl_up_sync(0xffffffff, pv, off);
            if (lane >= off) pv += o;
        }
        wsum[lane] = pv - v;   // exclusive warp offsets
    }
    __syncthreads();
    int excl = wsum[w] + ps - s;   // exclusive prefix for this thread
    if (t < 1000) {
        int base = t * 20;
        int run = excl;
#pragma unroll
        for (int k = 0; k < 20; k++) {
            g_rowptr[base + k] = run;
            run += local[k];
            g_cnt[base + k] = 0;     // reset for next call's count
            g_fill[base + k] = 0;    // reset for this call's scatter
        }
        if (t == 999) g_rowptr[Vn] = run;
    }
}

__global__ void scatter_kernel(const int* __restrict__ rows,
                               const int* __restrict__ cols,
                               const float* __restrict__ vals) {
    int j = blockIdx.x * blockDim.x + threadIdx.x;
    if (j < NNZn) {
        int r = rows[j];
        int p = g_rowptr[r] + atomicAdd(&g_fill[r], 1);
        __half2 h2 = __half2half2(__float2half_rn(vals[j]));
        g_ev[p] = make_int2(cols[j] << 8, *reinterpret_cast<int*>(&h2));  // uint4 row index (256/row)
    }
}

// ---------------- SpMM: y_out = L * y_in (pure power basis; no second operand) ----------------
__device__ __forceinline__ void hacc4(__half2* st, const uint4& r, __half2 w2) {
    const __half2* h = reinterpret_cast<const __half2*>(&r);
    st[0] = __hfma2(w2, h[0], st[0]);
    st[1] = __hfma2(w2, h[1], st[1]);
    st[2] = __hfma2(w2, h[2], st[2]);
    st[3] = __hfma2(w2, h[3], st[3]);
}

__device__ __forceinline__ void flush_st(float* acc, __half2* st) {
#pragma unroll
    for (int q = 0; q < 4; q++) {
        float2 fv = __half22float2(st[q]);
        acc[2 * q]     += fv.x;
        acc[2 * q + 1] += fv.y;
        st[q] = __half2half2(__ushort_as_half(0));
    }
}

__device__ __forceinline__ __half2 evw(const int2& ev) {
    return *reinterpret_cast<const __half2*>(&ev.y);
}

// grid: (Vn, 2), block: 128 threads, each thread one uint4 = 8 halves
__global__ void __launch_bounds__(128, 9) spmm_kernel(int iy, int io) {
    const unsigned term = (unsigned)Vn * 256;   // uint4 per term
    const uint4* __restrict__ y4 = reinterpret_cast<const uint4*>(g_xh) + (size_t)iy * term;
    uint4* __restrict__       o4 = reinterpret_cast<uint4*>(g_xh) + (size_t)io * term;

    int v = blockIdx.x;
    unsigned f = blockIdx.y * 128 + threadIdx.x;   // uint4 index 0..255 within the row
    int s = g_rowptr[v], e = g_rowptr[v + 1];

    float acc[8];
#pragma unroll
    for (int q = 0; q < 8; q++) acc[q] = 0.f;
    __half2 st[4];
#pragma unroll
    for (int q = 0; q < 4; q++) st[q] = __half2half2(__ushort_as_half(0));

    int j = s;
    for (; j + 7 < e; j += 8) {
        int2 ev0 = __ldg(&g_ev[j]);
        int2 ev1 = __ldg(&g_ev[j + 1]);
        int2 ev2 = __ldg(&g_ev[j + 2]);
        int2 ev3 = __ldg(&g_ev[j + 3]);
        int2 ev4 = __ldg(&g_ev[j + 4]);
        int2 ev5 = __ldg(&g_ev[j + 5]);
        int2 ev6 = __ldg(&g_ev[j + 6]);
        int2 ev7 = __ldg(&g_ev[j + 7]);
        {
            uint4 r0 = __ldg(&y4[(unsigned)ev0.x + f]);
            uint4 r1 = __ldg(&y4[(unsigned)ev1.x + f]);
            uint4 r2 = __ldg(&y4[(unsigned)ev2.x + f]);
            uint4 r3 = __ldg(&y4[(unsigned)ev3.x + f]);
            hacc4(st, r0, evw(ev0));
            hacc4(st, r1, evw(ev1));
            hacc4(st, r2, evw(ev2));
            hacc4(st, r3, evw(ev3));
        }
        {
            uint4 r0 = __ldg(&y4[(unsigned)ev4.x + f]);
            uint4 r1 = __ldg(&y4[(unsigned)ev5.x + f]);
            uint4 r2 = __ldg(&y4[(unsigned)ev6.x + f]);
            uint4 r3 = __ldg(&y4[(unsigned)ev7.x + f]);
            hacc4(st, r0, evw(ev4));
            hacc4(st, r1, evw(ev5));
            hacc4(st, r2, evw(ev6));
            hacc4(st, r3, evw(ev7));
        }
        flush_st(acc, st);
    }
    for (; j < e; j++) {
        int2 ev = __ldg(&g_ev[j]);
        uint4 r0 = __ldg(&y4[(unsigned)ev.x + f]);
        hacc4(st, r0, evw(ev));
    }
    flush_st(acc, st);

    size_t oi = (size_t)v * 256 + f;
    uint4 outv;
    __half2* oh = reinterpret_cast<__half2*>(&outv);
#pragma unroll
    for (int q = 0; q < 4; q++)
        oh[q] = __floats2half2_rn(acc[2 * q], acc[2 * q + 1]);
    __stcs(&o4[oi], outv);
}

// ---------------- fused fp16 GEMM: A via cp.async smem + ldmatrix, W via fragment LDG, direct stores ----------------
// out(b,o,v) = sum_{k,i} y_k[v][b*128+i] * W'[k][i][o] + bias[o]
#define MMA_F16(C, A, Bf)                                                                   \
    asm volatile("mma.sync.aligned.m16n8k16.row.col.f32.f16.f16.f32 "                      \
                 "{%0,%1,%2,%3},{%4,%5,%6,%7},{%8,%9},{%0,%1,%2,%3};"                       \
                 : "+f"((C)[0]), "+f"((C)[1]), "+f"((C)[2]), "+f"((C)[3])                   \
                 : "r"((A)[0]), "r"((A)[1]), "r"((A)[2]), "r"((A)[3]),                      \
                   "r"((Bf)[0]), "r"((Bf)[1]))

#define CP_ASYNC16(dst, src) \
    asm volatile("cp.async.cg.shared.global [%0], [%1], 16;" :: "r"(dst), "l"(src))
#define CP_COMMIT() asm volatile("cp.async.commit_group;")
#define CP_WAIT1()  asm volatile("cp.async.wait_group 1;")
#define CP_WAIT0()  asm volatile("cp.async.wait_group 0;")

#define LDSM_X4(r0, r1, r2, r3, addr) \
    asm volatile("ldmatrix.sync.aligned.m8n8.x4.shared.b16 {%0,%1,%2,%3}, [%4];" \
                 : "=r"(r0), "=r"(r1), "=r"(r2), "=r"(r3) : "r"(addr))

// block tile: M=128 (v), N=128 (o), K=512 in 16 chunks of 32 halves, 2-stage cp.async pipeline (A only).
// 256 threads = 8 warps (2 x 4). A stride 20 u32 (16B-aligned, ldmatrix conflict-free). Smem 20 KB.
__global__ void __launch_bounds__(256) gemm_kernel(const float* __restrict__ bias,
                                                   float* __restrict__ out) {
    __shared__ __align__(16) unsigned As[5120];     // [2][128][20] = 20 KB

    int tid  = threadIdx.x;
    int lane = tid & 31;
    int warp = tid >> 5;
    int wm   = warp & 1;
    int wn   = warp >> 1;  // 0..3 : 32 o-cols each
    int bb   = blockIdx.y;
    int v0   = blockIdx.x * 128;
    int t    = lane & 3;
    int g    = lane >> 2;

    uint32_t Asm = (uint32_t)__cvta_generic_to_shared(As);
    uint32_t a_lane = ((uint32_t)(wm * 16 + (lane & 15)) * 20u + ((lane >> 4) << 2)) * 4u;
    const uint4* wf = reinterpret_cast<const uint4*>(g_wtf) + ((size_t)wn * 32 + lane) * 4;

    float c[4][4][4];
#pragma unroll
    for (int nt = 0; nt < 4; nt++) {
        int o = wn * 32 + nt * 8 + t * 2;
        float b0 = bias[o], b1 = bias[o + 1];
#pragma unroll
        for (int mt = 0; mt < 4; mt++) {
            c[mt][nt][0] = b0; c[mt][nt][1] = b1;
            c[mt][nt][2] = b0; c[mt][nt][3] = b1;
        }
    }

    // stage issue: A rows clamp to row 0 when v >= Vn (finite garbage, never stored)
    auto issue = [&](int stg) {
        int buf = stg & 1;
        int r   = stg >> 2;          // term index (4 chunks of 32 per 128-wide term)
        int i0  = (stg & 3) * 32;    // offset within term's 128 features
#pragma unroll
        for (int p = 0; p < 2; p++) {
            int idx = tid + p * 256;      // 0..511
            int row = idx >> 2;
            int seg = idx & 3;
            int v   = v0 + row;
            int vc  = v < Vn ? v : 0;
            const __half* src = g_xh + (size_t)(r * Vn + vc) * Fn + bb * 128 + i0 + seg * 8;
            unsigned dst = (unsigned)__cvta_generic_to_shared(As + buf * 2560 + row * 20 + seg * 4);
            CP_ASYNC16(dst, src);
        }
        CP_COMMIT();
    };

    issue(0);
    for (int stg = 0; stg < 16; stg++) {
        // W' fragments for this stage: 4 coalesced LDG.128 from L2-hot g_wtf,
        // landing in ONE contiguous array (stage stride = 4*32*16 u32 = 512 uint4)
        uint4 w[4];
#pragma unroll
        for (int p = 0; p < 4; p++)
            w[p] = __ldg(&wf[(size_t)stg * 512 + p]);
        const unsigned* w_u = reinterpret_cast<const unsigned*>(w);

        if (stg + 1 < 16) {
            issue(stg + 1);
            CP_WAIT1();
        } else {
            CP_WAIT0();
        }
        __syncthreads();
        int buf = stg & 1;
        uint32_t Ab = Asm + (uint32_t)buf * 10240u + a_lane;
#pragma unroll
        for (int s = 0; s < 2; s++) {           // 2 k-steps of 16 halves
            const unsigned* q = w_u + s * 8;
            unsigned bf[4][2];
#pragma unroll
            for (int nt = 0; nt < 4; nt++) {
                bf[nt][0] = q[nt * 2];
                bf[nt][1] = q[nt * 2 + 1];
            }
#pragma unroll
            for (int mt = 0; mt < 4; mt++) {
                unsigned a[4];
                LDSM_X4(a[0], a[1], a[2], a[3], Ab + mt * 2560u + s * 32u);
#pragma unroll
                for (int nt = 0; nt < 4; nt++)
                    MMA_F16(c[mt][nt], a, bf[nt]);
            }
        }
        __syncthreads();
    }

    // direct stores: lanes with equal (lane&3) cover 8 consecutive v -> full 32B sectors
#pragma unroll
    for (int mt = 0; mt < 4; mt++) {
        int vr = v0 + mt * 32 + wm * 16 + g;
#pragma unroll
        for (int nt = 0; nt < 4; nt++) {
            int o = wn * 32 + nt * 8 + t * 2;
            size_t b0 = ((size_t)bb * 128 + o) * Vn;
            size_t b1 = ((size_t)bb * 128 + o + 1) * Vn;
            if (vr < Vn) {
                __stcs(&out[b0 + vr], c[mt][nt][0]);
                __stcs(&out[b1 + vr], c[mt][nt][1]);
            }
            if (vr + 8 < Vn) {
                __stcs(&out[b0 + vr + 8], c[mt][nt][2]);
                __stcs(&out[b1 + vr + 8], c[mt][nt][3]);
            }
        }
    }
}

// ---------------- launch (serial — nothing co-runs with the SpMM chain) ----------------
extern "C" void kernel_launch(void* const* d_in, const int* in_sizes, int n_in,
                              void* d_out, int out_size) {
    const float* x        = (const float*)d_in[0];
    const float* weight   = (const float*)d_in[1];
    const float* bias     = (const float*)d_in[2];
    const float* lap_vals = (const float*)d_in[3];
    const int*   lap_rows = (const int*)d_in[4];
    const int*   lap_cols = (const int*)d_in[5];
    float* out = (float*)d_out;

    // prelude: fused {count | transpose | wfrag}, scan (also resets counters), scatter
    fused_prelude_kernel<<<COUNT_BLKS + TRANS_BLKS + WPREP_BLKS, 256>>>(lap_rows, x, weight);
    scan_kernel<<<1, 1024>>>();
    scatter_kernel<<<NNZn / 256, 256>>>(lap_rows, lap_cols, lap_vals);

    // power basis: y1 = L y0 ; y2 = L y1 ; y3 = L y2 (recombination folded into W')
    spmm_kernel<<<dim3(Vn, 2), 128>>>(0, 1);
    spmm_kernel<<<dim3(Vn, 2), 128>>>(1, 2);
    spmm_kernel<<<dim3(Vn, 2), 128>>>(2, 3);

    // fused fp16 GEMM over all 4 power terms + bias, writes (B, Cout, V)
    gemm_kernel<<<dim3((Vn + 127) / 128, Bn), 256>>>(bias, out);
}